// round 8
// baseline (speedup 1.0000x reference)
#include <cuda_runtime.h>

// EdgeNetwork fused kernel, tf32 mma.sync version, round 7.
// vs round 6: W2 B-frags moved to smem (shared across warps) -> 128 regs freed,
// occupancy 2->4 blocks/SM; activation lo-split dropped (error margin 5x).

typedef unsigned long long u64;
#define DEVINL __device__ __forceinline__
#define FULLM 0xffffffffu

DEVINL u64 f2pack(float x, float y) {
    u64 d; asm("mov.b64 %0, {%1, %2};" : "=l"(d) : "f"(x), "f"(y)); return d;
}
DEVINL u64 f2fma(u64 a, u64 b, u64 c) {
    u64 d; asm("fma.rn.f32x2 %0, %1, %2, %3;" : "=l"(d) : "l"(a), "l"(b), "l"(c)); return d;
}
DEVINL u64 f2add(u64 a, u64 b) {
    u64 d; asm("add.rn.f32x2 %0, %1, %2;" : "=l"(d) : "l"(a), "l"(b)); return d;
}
DEVINL u64 f2dup(float x) { return f2pack(x, x); }
DEVINL unsigned tf32u(float x) {
    unsigned r; asm("cvt.rna.tf32.f32 %0, %1;" : "=r"(r) : "f"(x)); return r;
}
DEVINL void mma8(float* d, unsigned a0, unsigned a1, unsigned a2, unsigned a3,
                 unsigned b0, unsigned b1) {
    asm("mma.sync.aligned.m16n8k8.row.col.f32.tf32.tf32.f32 "
        "{%0,%1,%2,%3},{%4,%5,%6,%7},{%8,%9},{%0,%1,%2,%3};"
        : "+f"(d[0]), "+f"(d[1]), "+f"(d[2]), "+f"(d[3])
        : "r"(a0), "r"(a1), "r"(a2), "r"(a3), "r"(b0), "r"(b1));
}
DEVINL float leaky(float h) { return fmaxf(h, 0.1f * h); }

#define MAXN 50000
__device__ float g_P1[MAXN * 64];
__device__ float g_P2[MAXN * 64];

// ---------------------------------------------------------------------------
__global__ __launch_bounds__(256) void precompute_kernel(
    const float* __restrict__ NF, const float* __restrict__ W1,
    const float* __restrict__ b1, int n_nodes)
{
    __shared__ __align__(16) float sWa[4096];
    __shared__ __align__(16) float sWb[4096];
    __shared__ __align__(16) float sNF[8][68];

    int tid = threadIdx.x;
    for (int i = tid; i < 1024; i += 256) {
        ((float4*)sWa)[i] = ((const float4*)W1)[i];
        ((float4*)sWb)[i] = ((const float4*)(W1 + 4096))[i];
    }
    __syncthreads();

    int l = tid & 31, w = tid >> 5;
    int gw = blockIdx.x * 8 + w, totW = gridDim.x * 8;
    u64 b1p = f2pack(b1[2 * l], b1[2 * l + 1]);
    const u64* wa = (const u64*)sWa;
    const u64* wb = (const u64*)sWb;

    for (int n = gw; n < n_nodes && n < MAXN; n += totW) {
        float2 v = ((const float2*)(NF + (size_t)n * 64))[l];
        sNF[w][2 * l] = v.x; sNF[w][2 * l + 1] = v.y;
        __syncwarp();
        u64 acc1 = b1p, acc2 = 0ull;
        #pragma unroll
        for (int k4 = 0; k4 < 16; k4++) {
            float4 x = ((const float4*)sNF[w])[k4];
            int k = 4 * k4;
            u64 x0 = f2dup(x.x), x1 = f2dup(x.y), x2 = f2dup(x.z), x3 = f2dup(x.w);
            acc1 = f2fma(x0, wa[(k + 0) * 32 + l], acc1);
            acc2 = f2fma(x0, wb[(k + 0) * 32 + l], acc2);
            acc1 = f2fma(x1, wa[(k + 1) * 32 + l], acc1);
            acc2 = f2fma(x1, wb[(k + 1) * 32 + l], acc2);
            acc1 = f2fma(x2, wa[(k + 2) * 32 + l], acc1);
            acc2 = f2fma(x2, wb[(k + 2) * 32 + l], acc2);
            acc1 = f2fma(x3, wa[(k + 3) * 32 + l], acc1);
            acc2 = f2fma(x3, wb[(k + 3) * 32 + l], acc2);
        }
        ((u64*)(g_P1 + ((size_t)n << 6)))[l] = acc1;
        ((u64*)(g_P2 + ((size_t)n << 6)))[l] = acc2;
        __syncwarp();
    }
}

// ---------------------------------------------------------------------------
// edge_kernel: warp = 16 edges. r = lane>>2 (0..7), q = lane&3.
// C-frag of m16n8k8 tile m: (r,8m+2q),(r,8m+2q+1),(r+8,8m+2q),(r+8,8m+2q+1)
// ---------------------------------------------------------------------------
__global__ __launch_bounds__(128, 4) void edge_kernel(
    const int* __restrict__ EI, const float* __restrict__ EA,
    const float* __restrict__ W1, const float* __restrict__ W2,
    const float* __restrict__ g1, const float* __restrict__ be1,
    const float* __restrict__ b2, const float* __restrict__ g2,
    const float* __restrict__ be2, const float* __restrict__ W3,
    const float* __restrict__ b3, float* __restrict__ OUT, int E)
{
    __shared__ __align__(16) float sU[4][16][68];     // gathered U, pad 68
    __shared__ __align__(16) float sEA[4][16][20];    // edge_attr tile, pad 20
    __shared__ __align__(16) uint2 sW1c[2][8][8][5];  // W1c B frags, pad 5
    __shared__ __align__(16) uint2 sW2f[8][8][32];    // W2 B frags per lane, 16KB
    __shared__ __align__(16) float2 sQ1[64];          // (g1,be1) per col
    __shared__ __align__(16) float2 sB2p[32];         // b2 pairs
    __shared__ __align__(16) float4 sQ2[64];          // (g2,be2,w3,0) per col
    __shared__ float sB3;

    int tid = threadIdx.x;
    for (int i = tid; i < 64; i += 128) {
        sQ1[i] = make_float2(g1[i], be1[i]);
        sQ2[i] = make_float4(g2[i], be2[i], W3[i], 0.f);
    }
    for (int i = tid; i < 32; i += 128)
        sB2p[i] = make_float2(b2[2 * i], b2[2 * i + 1]);
    {
        const float* w1c = W1 + 128 * 64;
        for (int i = tid; i < 512; i += 128) {
            int qq = i & 3, rr = (i >> 2) & 7, mm = (i >> 5) & 7, jk = i >> 8;
            int col = 8 * mm + rr;
            sW1c[jk][mm][rr][qq] =
                make_uint2(tf32u(w1c[(8 * jk + qq) * 64 + col]),
                           tf32u(w1c[(8 * jk + qq + 4) * 64 + col]));
        }
    }
    // W2 B-frags (lane-indexed, shared by all warps):
    // sW2f[kt][m][lane] = { W2[8kt+2q][8m+r], W2[8kt+2q+1][8m+r] }
    for (int i = tid; i < 2048; i += 128) {
        int lane = i & 31, mm = (i >> 5) & 7, kt = i >> 8;
        int qq = lane & 3, rr = lane >> 2;
        int row0 = 8 * kt + 2 * qq, col = 8 * mm + rr;
        sW2f[kt][mm][lane] = make_uint2(tf32u(W2[row0 * 64 + col]),
                                        tf32u(W2[(row0 + 1) * 64 + col]));
    }
    if (tid == 0) sB3 = b3[0];
    __syncthreads();

    int l = tid & 31, w = tid >> 5;
    int q = l & 3, r = l >> 2;

    int gw = blockIdx.x * 4 + w, totW = gridDim.x * 4;
    int nG = (E + 15) >> 4;
    float bias3 = sB3;

    for (int g = gw; g < nG; g += totW) {
        int e0 = g << 4;

        // 1. indices: lanes 0-15 src(t=l), 16-31 dst(t=l-16)
        int colE = e0 + (l & 15); if (colE >= E) colE = E - 1;
        int idx = EI[(size_t)(l >> 4) * (size_t)E + (size_t)colE];

        // 2. gather U rows into smem (lane owns cols 2l,2l+1)
        #pragma unroll
        for (int t = 0; t < 16; t++) {
            int s = __shfl_sync(FULLM, idx, t);
            int d = __shfl_sync(FULLM, idx, 16 + t);
            u64 a = *(const u64*)(g_P1 + ((size_t)s << 6) + 2 * l);
            u64 b = *(const u64*)(g_P2 + ((size_t)d << 6) + 2 * l);
            *(u64*)&sU[w][t][2 * l] = f2add(a, b);
        }

        // 3. stage edge_attr 16x16
        if (e0 + 16 <= E) {
            const float4* base = (const float4*)(EA + (size_t)e0 * 16);
            float4 v0 = base[l], v1 = base[l + 32];
            int rr = l >> 2, cc = (l & 3) << 2;
            *(float4*)&sEA[w][rr][cc] = v0;
            *(float4*)&sEA[w][rr + 8][cc] = v1;
        } else if (l < 16) {
            int e = e0 + l; if (e >= E) e = E - 1;
            const float4* src = (const float4*)(EA + (size_t)e * 16);
            #pragma unroll
            for (int j = 0; j < 4; j++) *(float4*)&sEA[w][l][4 * j] = src[j];
        }
        __syncwarp();

        // 4. C init from U; ea @ W1c
        float D[8][4];
        #pragma unroll
        for (int m = 0; m < 8; m++) {
            float2 u01 = *(const float2*)&sU[w][r][8 * m + 2 * q];
            float2 u23 = *(const float2*)&sU[w][r + 8][8 * m + 2 * q];
            D[m][0] = u01.x; D[m][1] = u01.y; D[m][2] = u23.x; D[m][3] = u23.y;
        }
        #pragma unroll
        for (int jk = 0; jk < 2; jk++) {
            unsigned a0 = tf32u(sEA[w][r][8 * jk + q]);
            unsigned a1 = tf32u(sEA[w][r + 8][8 * jk + q]);
            unsigned a2 = tf32u(sEA[w][r][8 * jk + q + 4]);
            unsigned a3 = tf32u(sEA[w][r + 8][8 * jk + q + 4]);
            #pragma unroll
            for (int m = 0; m < 8; m++) {
                uint2 b = sW1c[jk][m][r][q];
                mma8(D[m], a0, a1, a2, a3, b.x, b.y);
            }
        }
        __syncwarp();   // smem reads done

        // 5. LN1 stats (rows r, r+8)
        float s0 = 0.f, s1 = 0.f, q0 = 0.f, q1 = 0.f;
        #pragma unroll
        for (int m = 0; m < 8; m++) {
            s0 += D[m][0] + D[m][1];
            q0 = fmaf(D[m][0], D[m][0], q0); q0 = fmaf(D[m][1], D[m][1], q0);
            s1 += D[m][2] + D[m][3];
            q1 = fmaf(D[m][2], D[m][2], q1); q1 = fmaf(D[m][3], D[m][3], q1);
        }
        s0 += __shfl_xor_sync(FULLM, s0, 1); s0 += __shfl_xor_sync(FULLM, s0, 2);
        q0 += __shfl_xor_sync(FULLM, q0, 1); q0 += __shfl_xor_sync(FULLM, q0, 2);
        s1 += __shfl_xor_sync(FULLM, s1, 1); s1 += __shfl_xor_sync(FULLM, s1, 2);
        q1 += __shfl_xor_sync(FULLM, q1, 1); q1 += __shfl_xor_sync(FULLM, q1, 2);
        float mu0 = s0 * 0.015625f;
        float rs0 = rsqrtf(fmaf(q0, 0.015625f, -mu0 * mu0) + 1e-5f);
        float mu1 = s1 * 0.015625f;
        float rs1 = rsqrtf(fmaf(q1, 0.015625f, -mu1 * mu1) + 1e-5f);

        // 6. LN1 + leaky; h @ W2 (C frag feeds A frag; B frags from smem)
        float D2[8][4];
        #pragma unroll
        for (int m = 0; m < 8; m++)
            { D2[m][0] = 0.f; D2[m][1] = 0.f; D2[m][2] = 0.f; D2[m][3] = 0.f; }

        #pragma unroll
        for (int kt = 0; kt < 8; kt++) {
            float4 gb = *(const float4*)&sQ1[8 * kt + 2 * q];
            float h0 = leaky(fmaf((D[kt][0] - mu0) * rs0, gb.x, gb.y));
            float h1 = leaky(fmaf((D[kt][1] - mu0) * rs0, gb.z, gb.w));
            float h2 = leaky(fmaf((D[kt][2] - mu1) * rs1, gb.x, gb.y));
            float h3 = leaky(fmaf((D[kt][3] - mu1) * rs1, gb.z, gb.w));
            unsigned a0 = tf32u(h0), a2 = tf32u(h1);
            unsigned a1 = tf32u(h2), a3 = tf32u(h3);
            #pragma unroll
            for (int m = 0; m < 8; m++) {
                uint2 bb = sW2f[kt][m][l];
                mma8(D2[m], a0, a1, a2, a3, bb.x, bb.y);
            }
        }

        // 7. +b2, LN2 stats
        s0 = 0.f; s1 = 0.f; q0 = 0.f; q1 = 0.f;
        #pragma unroll
        for (int m = 0; m < 8; m++) {
            float2 bb = sB2p[4 * m + q];
            D2[m][0] += bb.x; D2[m][1] += bb.y;
            D2[m][2] += bb.x; D2[m][3] += bb.y;
            s0 += D2[m][0] + D2[m][1];
            q0 = fmaf(D2[m][0], D2[m][0], q0); q0 = fmaf(D2[m][1], D2[m][1], q0);
            s1 += D2[m][2] + D2[m][3];
            q1 = fmaf(D2[m][2], D2[m][2], q1); q1 = fmaf(D2[m][3], D2[m][3], q1);
        }
        s0 += __shfl_xor_sync(FULLM, s0, 1); s0 += __shfl_xor_sync(FULLM, s0, 2);
        q0 += __shfl_xor_sync(FULLM, q0, 1); q0 += __shfl_xor_sync(FULLM, q0, 2);
        s1 += __shfl_xor_sync(FULLM, s1, 1); s1 += __shfl_xor_sync(FULLM, s1, 2);
        q1 += __shfl_xor_sync(FULLM, q1, 1); q1 += __shfl_xor_sync(FULLM, q1, 2);
        mu0 = s0 * 0.015625f;
        rs0 = rsqrtf(fmaf(q0, 0.015625f, -mu0 * mu0) + 1e-5f);
        mu1 = s1 * 0.015625f;
        rs1 = rsqrtf(fmaf(q1, 0.015625f, -mu1 * mu1) + 1e-5f);

        // 8. LN2 + leaky + W3 dot
        float acc0 = 0.f, acc1 = 0.f;
        #pragma unroll
        for (int m = 0; m < 8; m++) {
            float4 pa = sQ2[8 * m + 2 * q];
            float4 pb = sQ2[8 * m + 2 * q + 1];
            float h0 = leaky(fmaf((D2[m][0] - mu0) * rs0, pa.x, pa.y));
            float h1 = leaky(fmaf((D2[m][1] - mu0) * rs0, pb.x, pb.y));
            float h2 = leaky(fmaf((D2[m][2] - mu1) * rs1, pa.x, pa.y));
            float h3 = leaky(fmaf((D2[m][3] - mu1) * rs1, pb.x, pb.y));
            acc0 = fmaf(h0, pa.z, acc0); acc0 = fmaf(h1, pb.z, acc0);
            acc1 = fmaf(h2, pa.z, acc1); acc1 = fmaf(h3, pb.z, acc1);
        }
        acc0 += __shfl_xor_sync(FULLM, acc0, 1);
        acc0 += __shfl_xor_sync(FULLM, acc0, 2);
        acc1 += __shfl_xor_sync(FULLM, acc1, 1);
        acc1 += __shfl_xor_sync(FULLM, acc1, 2);

        if (q == 0) {
            int e = e0 + r;
            if (e < E) OUT[e] = acc0 + bias3;
            int e2 = e0 + 8 + r;
            if (e2 < E) OUT[e2] = acc1 + bias3;
        }
    }
}

// ---------------------------------------------------------------------------
extern "C" void kernel_launch(void* const* d_in, const int* in_sizes, int n_in,
                              void* d_out, int out_size)
{
    const float* NF  = (const float*)d_in[0];
    const int*   EI  = (const int*)d_in[1];        // (2,E) int32
    const float* EA  = (const float*)d_in[2];
    const float* W1  = (const float*)d_in[3];
    const float* b1  = (const float*)d_in[4];
    const float* g1  = (const float*)d_in[5];
    const float* be1 = (const float*)d_in[6];
    const float* W2  = (const float*)d_in[7];
    const float* b2  = (const float*)d_in[8];
    const float* g2  = (const float*)d_in[9];
    const float* be2 = (const float*)d_in[10];
    const float* W3  = (const float*)d_in[11];
    const float* b3  = (const float*)d_in[12];
    float* OUT = (float*)d_out;

    int n_nodes = in_sizes[0] / 64;
    int E       = in_sizes[1] / 2;
    if (E <= 0) return;

    precompute_kernel<<<592, 256>>>(NF, W1, b1, n_nodes);
    edge_kernel<<<592, 128>>>(EI, EA, W1, W2, g1, be1, b2, g2, be2, W3, b3, OUT, E);
}

// round 10
// speedup vs baseline: 1.6323x; 1.6323x over previous
#include <cuda_runtime.h>

// EdgeNetwork fused kernel, tf32 mma.sync, round 9.
// vs R6/R7: direct C-frag gather (no sU smem round trip), W2 B-frags split
// half-registers/half-smem, 3 blocks/SM (12 warps), index prefetch.

typedef unsigned long long u64;
#define DEVINL __device__ __forceinline__
#define FULLM 0xffffffffu

DEVINL u64 f2pack(float x, float y) {
    u64 d; asm("mov.b64 %0, {%1, %2};" : "=l"(d) : "f"(x), "f"(y)); return d;
}
DEVINL void f2unpack(u64 d, float &x, float &y) {
    asm("mov.b64 {%0, %1}, %2;" : "=f"(x), "=f"(y) : "l"(d));
}
DEVINL u64 f2fma(u64 a, u64 b, u64 c) {
    u64 d; asm("fma.rn.f32x2 %0, %1, %2, %3;" : "=l"(d) : "l"(a), "l"(b), "l"(c)); return d;
}
DEVINL u64 f2add(u64 a, u64 b) {
    u64 d; asm("add.rn.f32x2 %0, %1, %2;" : "=l"(d) : "l"(a), "l"(b)); return d;
}
DEVINL u64 f2dup(float x) { return f2pack(x, x); }
DEVINL unsigned tf32u(float x) {
    unsigned r; asm("cvt.rna.tf32.f32 %0, %1;" : "=r"(r) : "f"(x)); return r;
}
DEVINL void mma8(float* d, unsigned a0, unsigned a1, unsigned a2, unsigned a3,
                 unsigned b0, unsigned b1) {
    asm("mma.sync.aligned.m16n8k8.row.col.f32.tf32.tf32.f32 "
        "{%0,%1,%2,%3},{%4,%5,%6,%7},{%8,%9},{%0,%1,%2,%3};"
        : "+f"(d[0]), "+f"(d[1]), "+f"(d[2]), "+f"(d[3])
        : "r"(a0), "r"(a1), "r"(a2), "r"(a3), "r"(b0), "r"(b1));
}
DEVINL float leaky(float h) { return fmaxf(h, 0.1f * h); }

#define MAXN 50000
__device__ float g_P1[MAXN * 64];
__device__ float g_P2[MAXN * 64];

// ---------------------------------------------------------------------------
__global__ __launch_bounds__(256) void precompute_kernel(
    const float* __restrict__ NF, const float* __restrict__ W1,
    const float* __restrict__ b1, int n_nodes)
{
    __shared__ __align__(16) float sWa[4096];
    __shared__ __align__(16) float sWb[4096];
    __shared__ __align__(16) float sNF[8][68];

    int tid = threadIdx.x;
    for (int i = tid; i < 1024; i += 256) {
        ((float4*)sWa)[i] = ((const float4*)W1)[i];
        ((float4*)sWb)[i] = ((const float4*)(W1 + 4096))[i];
    }
    __syncthreads();

    int l = tid & 31, w = tid >> 5;
    int gw = blockIdx.x * 8 + w, totW = gridDim.x * 8;
    u64 b1p = f2pack(b1[2 * l], b1[2 * l + 1]);
    const u64* wa = (const u64*)sWa;
    const u64* wb = (const u64*)sWb;

    for (int n = gw; n < n_nodes && n < MAXN; n += totW) {
        float2 v = ((const float2*)(NF + (size_t)n * 64))[l];
        sNF[w][2 * l] = v.x; sNF[w][2 * l + 1] = v.y;
        __syncwarp();
        u64 acc1 = b1p, acc2 = 0ull;
        #pragma unroll
        for (int k4 = 0; k4 < 16; k4++) {
            float4 x = ((const float4*)sNF[w])[k4];
            int k = 4 * k4;
            u64 x0 = f2dup(x.x), x1 = f2dup(x.y), x2 = f2dup(x.z), x3 = f2dup(x.w);
            acc1 = f2fma(x0, wa[(k + 0) * 32 + l], acc1);
            acc2 = f2fma(x0, wb[(k + 0) * 32 + l], acc2);
            acc1 = f2fma(x1, wa[(k + 1) * 32 + l], acc1);
            acc2 = f2fma(x1, wb[(k + 1) * 32 + l], acc2);
            acc1 = f2fma(x2, wa[(k + 2) * 32 + l], acc1);
            acc2 = f2fma(x2, wb[(k + 2) * 32 + l], acc2);
            acc1 = f2fma(x3, wa[(k + 3) * 32 + l], acc1);
            acc2 = f2fma(x3, wb[(k + 3) * 32 + l], acc2);
        }
        ((u64*)(g_P1 + ((size_t)n << 6)))[l] = acc1;
        ((u64*)(g_P2 + ((size_t)n << 6)))[l] = acc2;
        __syncwarp();
    }
}

// ---------------------------------------------------------------------------
// edge_kernel: warp = 16 edges. r = lane>>2 (0..7), q = lane&3.
// C-frag of tile m: (r,8m+2q),(r,8m+2q+1),(r+8,8m+2q),(r+8,8m+2q+1)
// ---------------------------------------------------------------------------
__global__ __launch_bounds__(128, 3) void edge_kernel(
    const int* __restrict__ EI, const float* __restrict__ EA,
    const float* __restrict__ W1, const float* __restrict__ W2,
    const float* __restrict__ g1, const float* __restrict__ be1,
    const float* __restrict__ b2, const float* __restrict__ g2,
    const float* __restrict__ be2, const float* __restrict__ W3,
    const float* __restrict__ b3, float* __restrict__ OUT, int E)
{
    __shared__ __align__(16) float sEA[4][16][20];    // edge_attr tile, pad 20
    __shared__ __align__(16) uint2 sW1c[2][8][8][5];  // W1c B frags, pad 5
    __shared__ __align__(16) uint2 sW2f[4][8][32];    // W2 frags kt=4..7, 8KB
    __shared__ __align__(16) float2 sQ1[64];          // (g1,be1) per col
    __shared__ __align__(16) float2 sB2p[32];         // b2 pairs
    __shared__ __align__(16) float4 sQ2[64];          // (g2,be2,w3,0) per col
    __shared__ float sB3;

    int tid = threadIdx.x;
    for (int i = tid; i < 64; i += 128) {
        sQ1[i] = make_float2(g1[i], be1[i]);
        sQ2[i] = make_float4(g2[i], be2[i], W3[i], 0.f);
    }
    for (int i = tid; i < 32; i += 128)
        sB2p[i] = make_float2(b2[2 * i], b2[2 * i + 1]);
    {
        const float* w1c = W1 + 128 * 64;
        for (int i = tid; i < 512; i += 128) {
            int qq = i & 3, rr = (i >> 2) & 7, mm = (i >> 5) & 7, jk = i >> 8;
            int col = 8 * mm + rr;
            sW1c[jk][mm][rr][qq] =
                make_uint2(tf32u(w1c[(8 * jk + qq) * 64 + col]),
                           tf32u(w1c[(8 * jk + qq + 4) * 64 + col]));
        }
    }
    // W2 frags for kt=4..7 in smem: sW2f[kt-4][m][lane]
    for (int i = tid; i < 1024; i += 128) {
        int lane = i & 31, mm = (i >> 5) & 7, kt = (i >> 8) + 4;
        int qq = lane & 3, rr = lane >> 2;
        int row0 = 8 * kt + 2 * qq, col = 8 * mm + rr;
        sW2f[kt - 4][mm][lane] = make_uint2(tf32u(W2[row0 * 64 + col]),
                                            tf32u(W2[(row0 + 1) * 64 + col]));
    }
    if (tid == 0) sB3 = b3[0];
    __syncthreads();

    int l = tid & 31, w = tid >> 5;
    int q = l & 3, r = l >> 2;

    // W2 frags for kt=0..3 in registers (64 regs)
    unsigned w2r[4][8][2];
    #pragma unroll
    for (int kt = 0; kt < 4; kt++) {
        int row0 = 8 * kt + 2 * q;
        #pragma unroll
        for (int m = 0; m < 8; m++) {
            int col = 8 * m + r;
            w2r[kt][m][0] = tf32u(W2[row0 * 64 + col]);
            w2r[kt][m][1] = tf32u(W2[(row0 + 1) * 64 + col]);
        }
    }

    int gw = blockIdx.x * 4 + w, totW = gridDim.x * 4;
    int nG = (E + 15) >> 4;
    float bias3 = sB3;
    int lrow = (l >> 4);           // 0: src row of EI, 1: dst row
    int lt = l & 15;

    // prefetch first group's indices
    int idx = 0;
    if (gw < nG) {
        int colE = (gw << 4) + lt; if (colE >= E) colE = E - 1;
        idx = EI[(size_t)lrow * (size_t)E + (size_t)colE];
    }

    for (int g = gw; g < nG; g += totW) {
        int e0 = g << 4;

        // 1. distribute indices for rows r and r+8
        int sr  = __shfl_sync(FULLM, idx, r);
        int sr8 = __shfl_sync(FULLM, idx, r + 8);
        int dr  = __shfl_sync(FULLM, idx, 16 + r);
        int dr8 = __shfl_sync(FULLM, idx, 24 + r);

        const float* p1a = g_P1 + ((size_t)sr  << 6) + 2 * q;
        const float* p1b = g_P1 + ((size_t)sr8 << 6) + 2 * q;
        const float* p2a = g_P2 + ((size_t)dr  << 6) + 2 * q;
        const float* p2b = g_P2 + ((size_t)dr8 << 6) + 2 * q;

        // 2. direct C-frag gather: D[m] = U values this lane owns
        float D[8][4];
        #pragma unroll
        for (int m = 0; m < 8; m++) {
            u64 a  = *(const u64*)(p1a + 8 * m);
            u64 b  = *(const u64*)(p2a + 8 * m);
            u64 c  = *(const u64*)(p1b + 8 * m);
            u64 d_ = *(const u64*)(p2b + 8 * m);
            u64 u01 = f2add(a, b), u23 = f2add(c, d_);
            f2unpack(u01, D[m][0], D[m][1]);
            f2unpack(u23, D[m][2], D[m][3]);
        }

        // 3. stage edge_attr 16x16 (next iter's indices prefetched below)
        if (e0 + 16 <= E) {
            const float4* base = (const float4*)(EA + (size_t)e0 * 16);
            float4 v0 = base[l], v1 = base[l + 32];
            int rr = l >> 2, cc = (l & 3) << 2;
            *(float4*)&sEA[w][rr][cc] = v0;
            *(float4*)&sEA[w][rr + 8][cc] = v1;
        } else if (l < 16) {
            int e = e0 + l; if (e >= E) e = E - 1;
            const float4* src = (const float4*)(EA + (size_t)e * 16);
            #pragma unroll
            for (int j = 0; j < 4; j++) *(float4*)&sEA[w][l][4 * j] = src[j];
        }

        // prefetch next group's indices (independent load, hides latency)
        if (g + totW < nG) {
            int colE = ((g + totW) << 4) + lt; if (colE >= E) colE = E - 1;
            idx = EI[(size_t)lrow * (size_t)E + (size_t)colE];
        }
        __syncwarp();

        // 4. ea @ W1c accumulated into D
        #pragma unroll
        for (int jk = 0; jk < 2; jk++) {
            unsigned a0 = tf32u(sEA[w][r][8 * jk + q]);
            unsigned a1 = tf32u(sEA[w][r + 8][8 * jk + q]);
            unsigned a2 = tf32u(sEA[w][r][8 * jk + q + 4]);
            unsigned a3 = tf32u(sEA[w][r + 8][8 * jk + q + 4]);
            #pragma unroll
            for (int m = 0; m < 8; m++) {
                uint2 b = sW1c[jk][m][r][q];
                mma8(D[m], a0, a1, a2, a3, b.x, b.y);
            }
        }
        __syncwarp();   // sEA reads done

        // 5. LN1 stats (rows r, r+8)
        float s0 = 0.f, s1 = 0.f, q0 = 0.f, q1 = 0.f;
        #pragma unroll
        for (int m = 0; m < 8; m++) {
            s0 += D[m][0] + D[m][1];
            q0 = fmaf(D[m][0], D[m][0], q0); q0 = fmaf(D[m][1], D[m][1], q0);
            s1 += D[m][2] + D[m][3];
            q1 = fmaf(D[m][2], D[m][2], q1); q1 = fmaf(D[m][3], D[m][3], q1);
        }
        s0 += __shfl_xor_sync(FULLM, s0, 1); s0 += __shfl_xor_sync(FULLM, s0, 2);
        q0 += __shfl_xor_sync(FULLM, q0, 1); q0 += __shfl_xor_sync(FULLM, q0, 2);
        s1 += __shfl_xor_sync(FULLM, s1, 1); s1 += __shfl_xor_sync(FULLM, s1, 2);
        q1 += __shfl_xor_sync(FULLM, q1, 1); q1 += __shfl_xor_sync(FULLM, q1, 2);
        float mu0 = s0 * 0.015625f;
        float rs0 = rsqrtf(fmaf(q0, 0.015625f, -mu0 * mu0) + 1e-5f);
        float mu1 = s1 * 0.015625f;
        float rs1 = rsqrtf(fmaf(q1, 0.015625f, -mu1 * mu1) + 1e-5f);

        // 6. LN1 + leaky -> A frags (in place); h @ W2
        float D2[8][4];
        #pragma unroll
        for (int m = 0; m < 8; m++)
            { D2[m][0] = 0.f; D2[m][1] = 0.f; D2[m][2] = 0.f; D2[m][3] = 0.f; }

        #pragma unroll
        for (int kt = 0; kt < 8; kt++) {
            float4 gb = *(const float4*)&sQ1[8 * kt + 2 * q];
            float h0 = leaky(fmaf((D[kt][0] - mu0) * rs0, gb.x, gb.y));
            float h1 = leaky(fmaf((D[kt][1] - mu0) * rs0, gb.z, gb.w));
            float h2 = leaky(fmaf((D[kt][2] - mu1) * rs1, gb.x, gb.y));
            float h3 = leaky(fmaf((D[kt][3] - mu1) * rs1, gb.z, gb.w));
            unsigned a0 = tf32u(h0), a2 = tf32u(h1);
            unsigned a1 = tf32u(h2), a3 = tf32u(h3);
            if (kt < 4) {
                #pragma unroll
                for (int m = 0; m < 8; m++)
                    mma8(D2[m], a0, a1, a2, a3, w2r[kt][m][0], w2r[kt][m][1]);
            } else {
                #pragma unroll
                for (int m = 0; m < 8; m++) {
                    uint2 bb = sW2f[kt - 4][m][l];
                    mma8(D2[m], a0, a1, a2, a3, bb.x, bb.y);
                }
            }
        }

        // 7. +b2, LN2 stats
        s0 = 0.f; s1 = 0.f; q0 = 0.f; q1 = 0.f;
        #pragma unroll
        for (int m = 0; m < 8; m++) {
            float2 bb = sB2p[4 * m + q];
            D2[m][0] += bb.x; D2[m][1] += bb.y;
            D2[m][2] += bb.x; D2[m][3] += bb.y;
            s0 += D2[m][0] + D2[m][1];
            q0 = fmaf(D2[m][0], D2[m][0], q0); q0 = fmaf(D2[m][1], D2[m][1], q0);
            s1 += D2[m][2] + D2[m][3];
            q1 = fmaf(D2[m][2], D2[m][2], q1); q1 = fmaf(D2[m][3], D2[m][3], q1);
        }
        s0 += __shfl_xor_sync(FULLM, s0, 1); s0 += __shfl_xor_sync(FULLM, s0, 2);
        q0 += __shfl_xor_sync(FULLM, q0, 1); q0 += __shfl_xor_sync(FULLM, q0, 2);
        s1 += __shfl_xor_sync(FULLM, s1, 1); s1 += __shfl_xor_sync(FULLM, s1, 2);
        q1 += __shfl_xor_sync(FULLM, q1, 1); q1 += __shfl_xor_sync(FULLM, q1, 2);
        mu0 = s0 * 0.015625f;
        rs0 = rsqrtf(fmaf(q0, 0.015625f, -mu0 * mu0) + 1e-5f);
        mu1 = s1 * 0.015625f;
        rs1 = rsqrtf(fmaf(q1, 0.015625f, -mu1 * mu1) + 1e-5f);

        // 8. LN2 + leaky + W3 dot
        float acc0 = 0.f, acc1 = 0.f;
        #pragma unroll
        for (int m = 0; m < 8; m++) {
            float4 pa = sQ2[8 * m + 2 * q];
            float4 pb = sQ2[8 * m + 2 * q + 1];
            float h0 = leaky(fmaf((D2[m][0] - mu0) * rs0, pa.x, pa.y));
            float h1 = leaky(fmaf((D2[m][1] - mu0) * rs0, pb.x, pb.y));
            float h2 = leaky(fmaf((D2[m][2] - mu1) * rs1, pa.x, pa.y));
            float h3 = leaky(fmaf((D2[m][3] - mu1) * rs1, pb.x, pb.y));
            acc0 = fmaf(h0, pa.z, acc0); acc0 = fmaf(h1, pb.z, acc0);
            acc1 = fmaf(h2, pa.z, acc1); acc1 = fmaf(h3, pb.z, acc1);
        }
        acc0 += __shfl_xor_sync(FULLM, acc0, 1);
        acc0 += __shfl_xor_sync(FULLM, acc0, 2);
        acc1 += __shfl_xor_sync(FULLM, acc1, 1);
        acc1 += __shfl_xor_sync(FULLM, acc1, 2);

        if (q == 0) {
            int e = e0 + r;
            if (e < E) OUT[e] = acc0 + bias3;
            int e2 = e0 + 8 + r;
            if (e2 < E) OUT[e2] = acc1 + bias3;
        }
    }
}

// ---------------------------------------------------------------------------
extern "C" void kernel_launch(void* const* d_in, const int* in_sizes, int n_in,
                              void* d_out, int out_size)
{
    const float* NF  = (const float*)d_in[0];
    const int*   EI  = (const int*)d_in[1];        // (2,E) int32
    const float* EA  = (const float*)d_in[2];
    const float* W1  = (const float*)d_in[3];
    const float* b1  = (const float*)d_in[4];
    const float* g1  = (const float*)d_in[5];
    const float* be1 = (const float*)d_in[6];
    const float* W2  = (const float*)d_in[7];
    const float* b2  = (const float*)d_in[8];
    const float* g2  = (const float*)d_in[9];
    const float* be2 = (const float*)d_in[10];
    const float* W3  = (const float*)d_in[11];
    const float* b3  = (const float*)d_in[12];
    float* OUT = (float*)d_out;

    int n_nodes = in_sizes[0] / 64;
    int E       = in_sizes[1] / 2;
    if (E <= 0) return;

    precompute_kernel<<<592, 256>>>(NF, W1, b1, n_nodes);
    edge_kernel<<<444, 128>>>(EI, EA, W1, W2, g1, be1, b2, g2, be2, W3, b3, OUT, E);
}

// round 11
// speedup vs baseline: 1.8131x; 1.1108x over previous
#include <cuda_runtime.h>

// EdgeNetwork fused kernel, tf32 mma.sync, round 11.
// vs R9: P1/P2 stored in fragment-permuted order so the edge gather is
// 16x LDG.128 with one 128B line per row-visit (gather wavefronts halved).

typedef unsigned long long u64;
#define DEVINL __device__ __forceinline__
#define FULLM 0xffffffffu

DEVINL u64 f2pack(float x, float y) {
    u64 d; asm("mov.b64 %0, {%1, %2};" : "=l"(d) : "f"(x), "f"(y)); return d;
}
DEVINL u64 f2fma(u64 a, u64 b, u64 c) {
    u64 d; asm("fma.rn.f32x2 %0, %1, %2, %3;" : "=l"(d) : "l"(a), "l"(b), "l"(c)); return d;
}
DEVINL u64 f2dup(float x) { return f2pack(x, x); }
DEVINL unsigned tf32u(float x) {
    unsigned r; asm("cvt.rna.tf32.f32 %0, %1;" : "=r"(r) : "f"(x)); return r;
}
DEVINL void mma8(float* d, unsigned a0, unsigned a1, unsigned a2, unsigned a3,
                 unsigned b0, unsigned b1) {
    asm("mma.sync.aligned.m16n8k8.row.col.f32.tf32.tf32.f32 "
        "{%0,%1,%2,%3},{%4,%5,%6,%7},{%8,%9},{%0,%1,%2,%3};"
        : "+f"(d[0]), "+f"(d[1]), "+f"(d[2]), "+f"(d[3])
        : "r"(a0), "r"(a1), "r"(a2), "r"(a3), "r"(b0), "r"(b1));
}
DEVINL float leaky(float h) { return fmaxf(h, 0.1f * h); }

#define MAXN 50000
// Fragment-permuted layout: row n, u64 chunk index (j*8 + q*2 + hi) holds
// column pair for m = 2j+hi, q  (cols 8m+2q, 8m+2q+1).
__device__ float g_P1[MAXN * 64];
__device__ float g_P2[MAXN * 64];

// ---------------------------------------------------------------------------
// Kernel 1: per-node precompute; stores results in fragment-permuted order.
// Lane l computes col pair (2l, 2l+1): m = l>>2, q = l&3
//   -> dest u64 index = (m>>1)*8 + q*2 + (m&1)
// ---------------------------------------------------------------------------
__global__ __launch_bounds__(256) void precompute_kernel(
    const float* __restrict__ NF, const float* __restrict__ W1,
    const float* __restrict__ b1, int n_nodes)
{
    __shared__ __align__(16) float sWa[4096];
    __shared__ __align__(16) float sWb[4096];
    __shared__ __align__(16) float sNF[8][68];

    int tid = threadIdx.x;
    for (int i = tid; i < 1024; i += 256) {
        ((float4*)sWa)[i] = ((const float4*)W1)[i];
        ((float4*)sWb)[i] = ((const float4*)(W1 + 4096))[i];
    }
    __syncthreads();

    int l = tid & 31, w = tid >> 5;
    int gw = blockIdx.x * 8 + w, totW = gridDim.x * 8;
    u64 b1p = f2pack(b1[2 * l], b1[2 * l + 1]);
    const u64* wa = (const u64*)sWa;
    const u64* wb = (const u64*)sWb;

    // permuted destination index for this lane's column pair
    int pm = l >> 2, pq = l & 3;
    int dstIdx = ((pm >> 1) << 3) + (pq << 1) + (pm & 1);

    for (int n = gw; n < n_nodes && n < MAXN; n += totW) {
        float2 v = ((const float2*)(NF + (size_t)n * 64))[l];
        sNF[w][2 * l] = v.x; sNF[w][2 * l + 1] = v.y;
        __syncwarp();
        u64 acc1 = b1p, acc2 = 0ull;
        #pragma unroll
        for (int k4 = 0; k4 < 16; k4++) {
            float4 x = ((const float4*)sNF[w])[k4];
            int k = 4 * k4;
            u64 x0 = f2dup(x.x), x1 = f2dup(x.y), x2 = f2dup(x.z), x3 = f2dup(x.w);
            acc1 = f2fma(x0, wa[(k + 0) * 32 + l], acc1);
            acc2 = f2fma(x0, wb[(k + 0) * 32 + l], acc2);
            acc1 = f2fma(x1, wa[(k + 1) * 32 + l], acc1);
            acc2 = f2fma(x1, wb[(k + 1) * 32 + l], acc2);
            acc1 = f2fma(x2, wa[(k + 2) * 32 + l], acc1);
            acc2 = f2fma(x2, wb[(k + 2) * 32 + l], acc2);
            acc1 = f2fma(x3, wa[(k + 3) * 32 + l], acc1);
            acc2 = f2fma(x3, wb[(k + 3) * 32 + l], acc2);
        }
        ((u64*)(g_P1 + ((size_t)n << 6)))[dstIdx] = acc1;
        ((u64*)(g_P2 + ((size_t)n << 6)))[dstIdx] = acc2;
        __syncwarp();
    }
}

// ---------------------------------------------------------------------------
// edge_kernel: warp = 16 edges. r = lane>>2 (0..7), q = lane&3.
// C-frag of tile m: (r,8m+2q),(r,8m+2q+1),(r+8,8m+2q),(r+8,8m+2q+1)
// ---------------------------------------------------------------------------
__global__ __launch_bounds__(128, 3) void edge_kernel(
    const int* __restrict__ EI, const float* __restrict__ EA,
    const float* __restrict__ W1, const float* __restrict__ W2,
    const float* __restrict__ g1, const float* __restrict__ be1,
    const float* __restrict__ b2, const float* __restrict__ g2,
    const float* __restrict__ be2, const float* __restrict__ W3,
    const float* __restrict__ b3, float* __restrict__ OUT, int E)
{
    __shared__ __align__(16) float sEA[4][16][20];    // edge_attr tile, pad 20
    __shared__ __align__(16) uint2 sW1c[2][8][8][5];  // W1c B frags, pad 5
    __shared__ __align__(16) uint2 sW2f[4][8][32];    // W2 frags kt=4..7, 8KB
    __shared__ __align__(16) float2 sQ1[64];          // (g1,be1) per col
    __shared__ __align__(16) float2 sB2p[32];         // b2 pairs
    __shared__ __align__(16) float4 sQ2[64];          // (g2,be2,w3,0) per col
    __shared__ float sB3;

    int tid = threadIdx.x;
    for (int i = tid; i < 64; i += 128) {
        sQ1[i] = make_float2(g1[i], be1[i]);
        sQ2[i] = make_float4(g2[i], be2[i], W3[i], 0.f);
    }
    for (int i = tid; i < 32; i += 128)
        sB2p[i] = make_float2(b2[2 * i], b2[2 * i + 1]);
    {
        const float* w1c = W1 + 128 * 64;
        for (int i = tid; i < 512; i += 128) {
            int qq = i & 3, rr = (i >> 2) & 7, mm = (i >> 5) & 7, jk = i >> 8;
            int col = 8 * mm + rr;
            sW1c[jk][mm][rr][qq] =
                make_uint2(tf32u(w1c[(8 * jk + qq) * 64 + col]),
                           tf32u(w1c[(8 * jk + qq + 4) * 64 + col]));
        }
    }
    // W2 frags for kt=4..7 in smem: sW2f[kt-4][m][lane]
    for (int i = tid; i < 1024; i += 128) {
        int lane = i & 31, mm = (i >> 5) & 7, kt = (i >> 8) + 4;
        int qq = lane & 3, rr = lane >> 2;
        int row0 = 8 * kt + 2 * qq, col = 8 * mm + rr;
        sW2f[kt - 4][mm][lane] = make_uint2(tf32u(W2[row0 * 64 + col]),
                                            tf32u(W2[(row0 + 1) * 64 + col]));
    }
    if (tid == 0) sB3 = b3[0];
    __syncthreads();

    int l = tid & 31, w = tid >> 5;
    int q = l & 3, r = l >> 2;

    // W2 frags for kt=0..3 in registers (64 regs)
    unsigned w2r[4][8][2];
    #pragma unroll
    for (int kt = 0; kt < 4; kt++) {
        int row0 = 8 * kt + 2 * q;
        #pragma unroll
        for (int m = 0; m < 8; m++) {
            int col = 8 * m + r;
            w2r[kt][m][0] = tf32u(W2[row0 * 64 + col]);
            w2r[kt][m][1] = tf32u(W2[(row0 + 1) * 64 + col]);
        }
    }

    int gw = blockIdx.x * 4 + w, totW = gridDim.x * 4;
    int nG = (E + 15) >> 4;
    float bias3 = sB3;
    int lrow = (l >> 4);           // 0: src row of EI, 1: dst row
    int lt = l & 15;

    // prefetch first group's indices
    int idx = 0;
    if (gw < nG) {
        int colE = (gw << 4) + lt; if (colE >= E) colE = E - 1;
        idx = EI[(size_t)lrow * (size_t)E + (size_t)colE];
    }

    for (int g = gw; g < nG; g += totW) {
        int e0 = g << 4;

        // 1. distribute indices for rows r and r+8
        int sr  = __shfl_sync(FULLM, idx, r);
        int sr8 = __shfl_sync(FULLM, idx, r + 8);
        int dr  = __shfl_sync(FULLM, idx, 16 + r);
        int dr8 = __shfl_sync(FULLM, idx, 24 + r);

        // fragment-permuted rows: lane q reads float4 at offset 16j + 4q
        const float* p1a = g_P1 + ((size_t)sr  << 6) + 4 * q;
        const float* p1b = g_P1 + ((size_t)sr8 << 6) + 4 * q;
        const float* p2a = g_P2 + ((size_t)dr  << 6) + 4 * q;
        const float* p2b = g_P2 + ((size_t)dr8 << 6) + 4 * q;

        // 2. direct C-frag gather via LDG.128: each float4 covers m=2j, 2j+1
        float D[8][4];
        #pragma unroll
        for (int j = 0; j < 4; j++) {
            float4 A  = *(const float4*)(p1a + 16 * j);
            float4 B  = *(const float4*)(p2a + 16 * j);
            float4 Cc = *(const float4*)(p1b + 16 * j);
            float4 Dd = *(const float4*)(p2b + 16 * j);
            D[2*j  ][0] = A.x + B.x;  D[2*j  ][1] = A.y + B.y;
            D[2*j+1][0] = A.z + B.z;  D[2*j+1][1] = A.w + B.w;
            D[2*j  ][2] = Cc.x + Dd.x; D[2*j  ][3] = Cc.y + Dd.y;
            D[2*j+1][2] = Cc.z + Dd.z; D[2*j+1][3] = Cc.w + Dd.w;
        }

        // 3. stage edge_attr 16x16
        if (e0 + 16 <= E) {
            const float4* base = (const float4*)(EA + (size_t)e0 * 16);
            float4 v0 = base[l], v1 = base[l + 32];
            int rr = l >> 2, cc = (l & 3) << 2;
            *(float4*)&sEA[w][rr][cc] = v0;
            *(float4*)&sEA[w][rr + 8][cc] = v1;
        } else if (l < 16) {
            int e = e0 + l; if (e >= E) e = E - 1;
            const float4* src = (const float4*)(EA + (size_t)e * 16);
            #pragma unroll
            for (int j = 0; j < 4; j++) *(float4*)&sEA[w][l][4 * j] = src[j];
        }

        // prefetch next group's indices (independent load, hides latency)
        if (g + totW < nG) {
            int colE = ((g + totW) << 4) + lt; if (colE >= E) colE = E - 1;
            idx = EI[(size_t)lrow * (size_t)E + (size_t)colE];
        }
        __syncwarp();

        // 4. ea @ W1c accumulated into D
        #pragma unroll
        for (int jk = 0; jk < 2; jk++) {
            unsigned a0 = tf32u(sEA[w][r][8 * jk + q]);
            unsigned a1 = tf32u(sEA[w][r + 8][8 * jk + q]);
            unsigned a2 = tf32u(sEA[w][r][8 * jk + q + 4]);
            unsigned a3 = tf32u(sEA[w][r + 8][8 * jk + q + 4]);
            #pragma unroll
            for (int m = 0; m < 8; m++) {
                uint2 b = sW1c[jk][m][r][q];
                mma8(D[m], a0, a1, a2, a3, b.x, b.y);
            }
        }
        __syncwarp();   // sEA reads done

        // 5. LN1 stats (rows r, r+8)
        float s0 = 0.f, s1 = 0.f, q0 = 0.f, q1 = 0.f;
        #pragma unroll
        for (int m = 0; m < 8; m++) {
            s0 += D[m][0] + D[m][1];
            q0 = fmaf(D[m][0], D[m][0], q0); q0 = fmaf(D[m][1], D[m][1], q0);
            s1 += D[m][2] + D[m][3];
            q1 = fmaf(D[m][2], D[m][2], q1); q1 = fmaf(D[m][3], D[m][3], q1);
        }
        s0 += __shfl_xor_sync(FULLM, s0, 1); s0 += __shfl_xor_sync(FULLM, s0, 2);
        q0 += __shfl_xor_sync(FULLM, q0, 1); q0 += __shfl_xor_sync(FULLM, q0, 2);
        s1 += __shfl_xor_sync(FULLM, s1, 1); s1 += __shfl_xor_sync(FULLM, s1, 2);
        q1 += __shfl_xor_sync(FULLM, q1, 1); q1 += __shfl_xor_sync(FULLM, q1, 2);
        float mu0 = s0 * 0.015625f;
        float rs0 = rsqrtf(fmaf(q0, 0.015625f, -mu0 * mu0) + 1e-5f);
        float mu1 = s1 * 0.015625f;
        float rs1 = rsqrtf(fmaf(q1, 0.015625f, -mu1 * mu1) + 1e-5f);

        // 6. LN1 + leaky -> A frags; h @ W2
        float D2[8][4];
        #pragma unroll
        for (int m = 0; m < 8; m++)
            { D2[m][0] = 0.f; D2[m][1] = 0.f; D2[m][2] = 0.f; D2[m][3] = 0.f; }

        #pragma unroll
        for (int kt = 0; kt < 8; kt++) {
            float4 gb = *(const float4*)&sQ1[8 * kt + 2 * q];
            float h0 = leaky(fmaf((D[kt][0] - mu0) * rs0, gb.x, gb.y));
            float h1 = leaky(fmaf((D[kt][1] - mu0) * rs0, gb.z, gb.w));
            float h2 = leaky(fmaf((D[kt][2] - mu1) * rs1, gb.x, gb.y));
            float h3 = leaky(fmaf((D[kt][3] - mu1) * rs1, gb.z, gb.w));
            unsigned a0 = tf32u(h0), a2 = tf32u(h1);
            unsigned a1 = tf32u(h2), a3 = tf32u(h3);
            if (kt < 4) {
                #pragma unroll
                for (int m = 0; m < 8; m++)
                    mma8(D2[m], a0, a1, a2, a3, w2r[kt][m][0], w2r[kt][m][1]);
            } else {
                #pragma unroll
                for (int m = 0; m < 8; m++) {
                    uint2 bb = sW2f[kt - 4][m][l];
                    mma8(D2[m], a0, a1, a2, a3, bb.x, bb.y);
                }
            }
        }

        // 7. +b2, LN2 stats
        s0 = 0.f; s1 = 0.f; q0 = 0.f; q1 = 0.f;
        #pragma unroll
        for (int m = 0; m < 8; m++) {
            float2 bb = sB2p[4 * m + q];
            D2[m][0] += bb.x; D2[m][1] += bb.y;
            D2[m][2] += bb.x; D2[m][3] += bb.y;
            s0 += D2[m][0] + D2[m][1];
            q0 = fmaf(D2[m][0], D2[m][0], q0); q0 = fmaf(D2[m][1], D2[m][1], q0);
            s1 += D2[m][2] + D2[m][3];
            q1 = fmaf(D2[m][2], D2[m][2], q1); q1 = fmaf(D2[m][3], D2[m][3], q1);
        }
        s0 += __shfl_xor_sync(FULLM, s0, 1); s0 += __shfl_xor_sync(FULLM, s0, 2);
        q0 += __shfl_xor_sync(FULLM, q0, 1); q0 += __shfl_xor_sync(FULLM, q0, 2);
        s1 += __shfl_xor_sync(FULLM, s1, 1); s1 += __shfl_xor_sync(FULLM, s1, 2);
        q1 += __shfl_xor_sync(FULLM, q1, 1); q1 += __shfl_xor_sync(FULLM, q1, 2);
        mu0 = s0 * 0.015625f;
        rs0 = rsqrtf(fmaf(q0, 0.015625f, -mu0 * mu0) + 1e-5f);
        mu1 = s1 * 0.015625f;
        rs1 = rsqrtf(fmaf(q1, 0.015625f, -mu1 * mu1) + 1e-5f);

        // 8. LN2 + leaky + W3 dot
        float acc0 = 0.f, acc1 = 0.f;
        #pragma unroll
        for (int m = 0; m < 8; m++) {
            float4 pa = sQ2[8 * m + 2 * q];
            float4 pb = sQ2[8 * m + 2 * q + 1];
            float h0 = leaky(fmaf((D2[m][0] - mu0) * rs0, pa.x, pa.y));
            float h1 = leaky(fmaf((D2[m][1] - mu0) * rs0, pb.x, pb.y));
            float h2 = leaky(fmaf((D2[m][2] - mu1) * rs1, pa.x, pa.y));
            float h3 = leaky(fmaf((D2[m][3] - mu1) * rs1, pb.x, pb.y));
            acc0 = fmaf(h0, pa.z, acc0); acc0 = fmaf(h1, pb.z, acc0);
            acc1 = fmaf(h2, pa.z, acc1); acc1 = fmaf(h3, pb.z, acc1);
        }
        acc0 += __shfl_xor_sync(FULLM, acc0, 1);
        acc0 += __shfl_xor_sync(FULLM, acc0, 2);
        acc1 += __shfl_xor_sync(FULLM, acc1, 1);
        acc1 += __shfl_xor_sync(FULLM, acc1, 2);

        if (q == 0) {
            int e = e0 + r;
            if (e < E) OUT[e] = acc0 + bias3;
            int e2 = e0 + 8 + r;
            if (e2 < E) OUT[e2] = acc1 + bias3;
        }
    }
}

// ---------------------------------------------------------------------------
extern "C" void kernel_launch(void* const* d_in, const int* in_sizes, int n_in,
                              void* d_out, int out_size)
{
    const float* NF  = (const float*)d_in[0];
    const int*   EI  = (const int*)d_in[1];        // (2,E) int32
    const float* EA  = (const float*)d_in[2];
    const float* W1  = (const float*)d_in[3];
    const float* b1  = (const float*)d_in[4];
    const float* g1  = (const float*)d_in[5];
    const float* be1 = (const float*)d_in[6];
    const float* W2  = (const float*)d_in[7];
    const float* b2  = (const float*)d_in[8];
    const float* g2  = (const float*)d_in[9];
    const float* be2 = (const float*)d_in[10];
    const float* W3  = (const float*)d_in[11];
    const float* b3  = (const float*)d_in[12];
    float* OUT = (float*)d_out;

    int n_nodes = in_sizes[0] / 64;
    int E       = in_sizes[1] / 2;
    if (E <= 0) return;

    precompute_kernel<<<592, 256>>>(NF, W1, b1, n_nodes);
    edge_kernel<<<444, 128>>>(EI, EA, W1, W2, g1, be1, b2, g2, be2, W3, b3, OUT, E);
}